// round 15
// baseline (speedup 1.0000x reference)
#include <cuda_runtime.h>
#include <cuda_fp16.h>
#include <math.h>

#define MAXN 100000
#define MAXE 1600000
#define EPS 1e-16f

// ------------------------ scratch (device globals, no allocs) ---------------
__device__ __half g_h1h[MAXN * 128];     // layer-1 node projections (fp16)
__device__ float  g_asrc1[MAXN * 2];
__device__ float  g_adst1[MAXN * 2];

__device__ float4 g_node2[MAXN];         // {h2p0, h2p1, asrc2, adst2}

__device__ float g_weatt1[6];            // [head][k] folded edge-attn weights
__device__ float g_weatt2[3];

// CSR structures (rebuilt every call — deterministic work)
// g_deg is zero on entry (zero-initialized at load; re-zeroed by k_scan3 each call)
__device__ int  g_deg[MAXN];
__device__ int  g_rowptr[MAXN + 1];
__device__ int  g_cursor[MAXN];
__device__ int  g_blocksum[256];
__device__ int4 g_csr[MAXE];             // {src, f2i(ae0), f2i(ae1), f2i(edot2)}

// ------------------------ helpers -------------------------------------------
static __device__ __forceinline__ float leaky(float a) { return a > 0.f ? a : 0.2f * a; }

static __device__ __forceinline__ unsigned h2_bits(__half2 h) {
    union { __half2 h; unsigned u; } cvt;
    cvt.h = h;
    return cvt.u;
}

static __device__ __forceinline__ float to_tf32(float f) {
    float r;
    asm("cvt.rna.tf32.f32 %0, %1;" : "=f"(r) : "f"(f));
    return r;
}

static __device__ __forceinline__ void mma_tf32(float* c, float a0, float a1, float a2,
                                                float a3, float b0, float b1) {
    unsigned ua0 = __float_as_uint(a0), ua1 = __float_as_uint(a1);
    unsigned ua2 = __float_as_uint(a2), ua3 = __float_as_uint(a3);
    unsigned ub0 = __float_as_uint(b0), ub1 = __float_as_uint(b1);
    asm volatile(
        "mma.sync.aligned.m16n8k8.row.col.f32.tf32.tf32.f32 "
        "{%0,%1,%2,%3}, {%4,%5,%6,%7}, {%8,%9}, {%0,%1,%2,%3};"
        : "+f"(c[0]), "+f"(c[1]), "+f"(c[2]), "+f"(c[3])
        : "r"(ua0), "r"(ua1), "r"(ua2), "r"(ua3), "r"(ub0), "r"(ub1));
}

// ------------------------ K1: h1 = x @ W1 via tf32 mma + fused att dots -----
#define GBM 128
__global__ __launch_bounds__(256) void k_gemm1(const float* __restrict__ x,
                                               const float* __restrict__ W,
                                               const float* __restrict__ as1,
                                               const float* __restrict__ ad1, int N) {
    __shared__ float xs[GBM][33];    // tf32-rounded x tile
    __shared__ float ws[32][132];    // tf32-rounded W tile
    const int tid = threadIdx.x;
    const int warp = tid >> 5, lane = tid & 31;
    const int lg = lane >> 2;        // group 0..7 (row within fragment)
    const int lt = lane & 3;         // thread in group
    const int rowBase = blockIdx.x * GBM;
    const int wr = warp * 16;        // warp's row offset within tile

    float acc[16][4];
#pragma unroll
    for (int i = 0; i < 16; i++)
        acc[i][0] = acc[i][1] = acc[i][2] = acc[i][3] = 0.f;

    for (int k0 = 0; k0 < 128; k0 += 32) {
        for (int i = tid; i < GBM * 8; i += 256) {
            int r = i >> 3, c4 = (i & 7) * 4;
            int gr = rowBase + r;
            float4 v = (gr < N) ? *(const float4*)&x[(long)gr * 128 + k0 + c4]
                                : make_float4(0.f, 0.f, 0.f, 0.f);
            xs[r][c4 + 0] = to_tf32(v.x); xs[r][c4 + 1] = to_tf32(v.y);
            xs[r][c4 + 2] = to_tf32(v.z); xs[r][c4 + 3] = to_tf32(v.w);
        }
        for (int i = tid; i < 32 * 32; i += 256) {
            int r = i >> 5, c4 = (i & 31) * 4;
            float4 v = *(const float4*)&W[(long)(k0 + r) * 128 + c4];
            ws[r][c4 + 0] = to_tf32(v.x); ws[r][c4 + 1] = to_tf32(v.y);
            ws[r][c4 + 2] = to_tf32(v.z); ws[r][c4 + 3] = to_tf32(v.w);
        }
        __syncthreads();
#pragma unroll
        for (int kk = 0; kk < 32; kk += 8) {
            int ar = wr + lg, ac = kk + lt;
            float a0 = xs[ar][ac],     a1 = xs[ar + 8][ac];
            float a2 = xs[ar][ac + 4], a3 = xs[ar + 8][ac + 4];
#pragma unroll
            for (int nt = 0; nt < 16; nt++) {
                float b0 = ws[kk + lt][nt * 8 + lg];
                float b1 = ws[kk + 4 + lt][nt * 8 + lg];
                mma_tf32(acc[nt], a0, a1, a2, a3, b0, b1);
            }
        }
        __syncthreads();
    }

    // epilogue: fp16 store + attention dot products
    int rA = rowBase + wr + lg;
    int rB = rA + 8;
    float sA0 = 0.f, sA1 = 0.f, dA0 = 0.f, dA1 = 0.f;
    float sB0 = 0.f, sB1 = 0.f, dB0 = 0.f, dB1 = 0.f;
#pragma unroll
    for (int nt = 0; nt < 16; nt++) {
        int col = nt * 8 + lt * 2;
        if (rA < N)
            *(unsigned*)&g_h1h[(long)rA * 128 + col] =
                h2_bits(__floats2half2_rn(acc[nt][0], acc[nt][1]));
        if (rB < N)
            *(unsigned*)&g_h1h[(long)rB * 128 + col] =
                h2_bits(__floats2half2_rn(acc[nt][2], acc[nt][3]));
        float as0 = __ldg(&as1[col]), as1v = __ldg(&as1[col + 1]);
        float ad0 = __ldg(&ad1[col]), ad1v = __ldg(&ad1[col + 1]);
        if (nt < 8) {
            sA0 += acc[nt][0] * as0 + acc[nt][1] * as1v;
            dA0 += acc[nt][0] * ad0 + acc[nt][1] * ad1v;
            sB0 += acc[nt][2] * as0 + acc[nt][3] * as1v;
            dB0 += acc[nt][2] * ad0 + acc[nt][3] * ad1v;
        } else {
            sA1 += acc[nt][0] * as0 + acc[nt][1] * as1v;
            dA1 += acc[nt][0] * ad0 + acc[nt][1] * ad1v;
            sB1 += acc[nt][2] * as0 + acc[nt][3] * as1v;
            dB1 += acc[nt][2] * ad0 + acc[nt][3] * ad1v;
        }
    }
#pragma unroll
    for (int off = 1; off <= 2; off <<= 1) {
        sA0 += __shfl_xor_sync(0xffffffffu, sA0, off);
        sA1 += __shfl_xor_sync(0xffffffffu, sA1, off);
        dA0 += __shfl_xor_sync(0xffffffffu, dA0, off);
        dA1 += __shfl_xor_sync(0xffffffffu, dA1, off);
        sB0 += __shfl_xor_sync(0xffffffffu, sB0, off);
        sB1 += __shfl_xor_sync(0xffffffffu, sB1, off);
        dB0 += __shfl_xor_sync(0xffffffffu, dB0, off);
        dB1 += __shfl_xor_sync(0xffffffffu, dB1, off);
    }
    if (lt == 0) {
        if (rA < N) {
            g_asrc1[rA * 2] = sA0; g_asrc1[rA * 2 + 1] = sA1;
            g_adst1[rA * 2] = dA0; g_adst1[rA * 2 + 1] = dA1;
        }
        if (rB < N) {
            g_asrc1[rB * 2] = sB0; g_asrc1[rB * 2 + 1] = sB1;
            g_adst1[rB * 2] = dB0; g_adst1[rB * 2 + 1] = dB1;
        }
    }
}

// ------------------------ CSR build ------------------------------------------
// scalar hist; block 0 folds the edge-attention weights IN PARALLEL
// (warps 0-5: one 64-length dot each via shfl reduction; warp 6: layer-2 fold)
__global__ __launch_bounds__(256) void k_hist(const int* __restrict__ ei,
                                              const float* __restrict__ We1,
                                              const float* __restrict__ ae1,
                                              const float* __restrict__ We2,
                                              const float* __restrict__ ae2, int E) {
    int e = blockIdx.x * blockDim.x + threadIdx.x;
    if (e < E) atomicAdd(&g_deg[__ldg(&ei[E + e])], 1);
    if (blockIdx.x == 0) {
        int warp = threadIdx.x >> 5, lane = threadIdx.x & 31;
        if (warp < 6) {
            int h = warp / 3, k = warp % 3;   // g_weatt1 index = h*3+k = warp
            float s = We1[k * 128 + h * 64 + lane]      * ae1[h * 64 + lane]
                    + We1[k * 128 + h * 64 + lane + 32] * ae1[h * 64 + lane + 32];
#pragma unroll
            for (int off = 16; off; off >>= 1)
                s += __shfl_xor_sync(0xffffffffu, s, off);
            if (lane == 0) g_weatt1[warp] = s;
        } else if (warp == 6 && lane < 3) {
            g_weatt2[lane] = We2[lane * 2 + 0] * ae2[0] + We2[lane * 2 + 1] * ae2[1];
        }
    }
}

__global__ __launch_bounds__(256) void k_scan1(int N) {
    __shared__ int ssum[256];
    int t = threadIdx.x;
    int base = blockIdx.x * 1024;
    int idx = base + t * 4;
    int v0 = 0, v1 = 0, v2 = 0, v3 = 0;
    if (idx + 3 < N) {
        int4 v = *(const int4*)&g_deg[idx];
        v0 = v.x; v1 = v.y; v2 = v.z; v3 = v.w;
    } else {
        if (idx + 0 < N) v0 = g_deg[idx + 0];
        if (idx + 1 < N) v1 = g_deg[idx + 1];
        if (idx + 2 < N) v2 = g_deg[idx + 2];
        if (idx + 3 < N) v3 = g_deg[idx + 3];
    }
    int s0 = v0, s1 = s0 + v1, s2 = s1 + v2, s3 = s2 + v3;
    ssum[t] = s3;
    __syncthreads();
    for (int off = 1; off < 256; off <<= 1) {
        int add = (t >= off) ? ssum[t - off] : 0;
        __syncthreads();
        ssum[t] += add;
        __syncthreads();
    }
    int texcl = t ? ssum[t - 1] : 0;
    if (idx + 0 < N) g_rowptr[idx + 0] = texcl;
    if (idx + 1 < N) g_rowptr[idx + 1] = texcl + s0;
    if (idx + 2 < N) g_rowptr[idx + 2] = texcl + s1;
    if (idx + 3 < N) g_rowptr[idx + 3] = texcl + s2;
    if (t == 255) g_blocksum[blockIdx.x] = ssum[255];
}

// scan3 folds in the inter-block offset (prefix of blocksum) per block, and
// re-zeroes g_deg (already consumed by scan1) so the next call starts clean.
__global__ __launch_bounds__(256) void k_scan3(int N, int E) {
    __shared__ int sh[256];
    int t = threadIdx.x;
    int bucket = blockIdx.x >> 2;              // scan1 block containing this range
    sh[t] = (t < bucket) ? g_blocksum[t] : 0;  // bucket <= 97 < 256
    __syncthreads();
#pragma unroll
    for (int off = 128; off; off >>= 1) {
        if (t < off) sh[t] += sh[t + off];
        __syncthreads();
    }
    int offset = sh[0];
    int n = blockIdx.x * 256 + t;
    if (n < N) {
        int v = g_rowptr[n] + offset;
        g_rowptr[n] = v;
        g_cursor[n] = v;
        g_deg[n] = 0;                          // ready for next replay
    }
    if (blockIdx.x == 0 && t == 0) g_rowptr[N] = E;
}

// scatter (R9 form): computes exp(alpha) per head here, where adst1[d]/asrc1[s]
// gathers overlap the scattered store; payload is {src, ae0, ae1, edot2}.
__global__ __launch_bounds__(256) void k_scatter(const int* __restrict__ ei,
                                                 const float* __restrict__ ea, int E) {
    int e = blockIdx.x * blockDim.x + threadIdx.x;
    if (e >= E) return;
    int s = __ldg(&ei[e]), d = __ldg(&ei[E + e]);
    float e0 = __ldg(&ea[e * 3]), e1 = __ldg(&ea[e * 3 + 1]), e2 = __ldg(&ea[e * 3 + 2]);
    float2 asv = *(const float2*)&g_asrc1[s * 2];
    float2 adv = *(const float2*)&g_adst1[d * 2];
    float ae0 = __expf(leaky(asv.x + adv.x +
                  e0 * g_weatt1[0] + e1 * g_weatt1[1] + e2 * g_weatt1[2]));
    float ae1 = __expf(leaky(asv.y + adv.y +
                  e0 * g_weatt1[3] + e1 * g_weatt1[4] + e2 * g_weatt1[5]));
    float edot2 = e0 * g_weatt2[0] + e1 * g_weatt2[1] + e2 * g_weatt2[2];
    int pos = atomicAdd(&g_cursor[d], 1);
    g_csr[pos] = make_int4(s, __float_as_int(ae0), __float_as_int(ae1), __float_as_int(edot2));
}

// ------------------------ K3: fused layer-1 aggregate + ELU + layer-2 proj --
// one warp per dst node, HALF-WARP per edge: lane covers 8 fp16 channels
// (16B load), two edges in flight per iteration, register accumulation.
// (EXACT Round-9 body; epilogue writes the packed float4 node record.)
__global__ __launch_bounds__(256) void k_agg1(const float* __restrict__ b1,
                                              const float* __restrict__ W2,
                                              const float* __restrict__ as2,
                                              const float* __restrict__ ad2, int N) {
    int w = (blockIdx.x * blockDim.x + threadIdx.x) >> 5;
    int lane = threadIdx.x & 31;
    if (w >= N) return;
    const int half = lane >> 4;          // 0 = slot A, 1 = slot B
    const int hl = lane & 15;            // lane within half
    const int c8 = hl * 8;               // 8 fp16 channels starting here
    const int h = hl >> 3;               // head of these channels
    int beg = g_rowptr[w], end = g_rowptr[w + 1];

    float acc[8];
    float den = 0.f;

    // self-loop term: accumulated by half A only (merged via shfl_xor(16) later)
    {
        float2 asv = *(const float2*)&g_asrc1[w * 2];
        float2 adv = *(const float2*)&g_adst1[w * 2];
        float es0 = __expf(leaky(asv.x + adv.x));
        float es1 = __expf(leaky(asv.y + adv.y));
        float es = h ? es1 : es0;
        if (half == 0) {
            den = es;
            uint4 pk = *(const uint4*)&g_h1h[(long)w * 128 + c8];
            float2 p0 = __half22float2(*(const __half2*)&pk.x);
            float2 p1 = __half22float2(*(const __half2*)&pk.y);
            float2 p2 = __half22float2(*(const __half2*)&pk.z);
            float2 p3 = __half22float2(*(const __half2*)&pk.w);
            acc[0] = p0.x * es; acc[1] = p0.y * es;
            acc[2] = p1.x * es; acc[3] = p1.y * es;
            acc[4] = p2.x * es; acc[5] = p2.y * es;
            acc[6] = p3.x * es; acc[7] = p3.y * es;
        } else {
#pragma unroll
            for (int k = 0; k < 8; k++) acc[k] = 0.f;
        }
    }

    for (int i0 = beg; i0 < end; i0 += 32) {
        int nthis = min(32, end - i0);
        int iters = (nthis + 1) >> 1;        // warp-uniform trip count
        int4 pl = make_int4(0, 0, 0, 0);
        if (lane < nthis) pl = __ldg(&g_csr[i0 + lane]);
#pragma unroll 4
        for (int t = 0; t < iters; t++) {
            int srcLane = 2 * t + half;      // my half's edge in this pair
            int   s   = __shfl_sync(0xffffffffu, pl.x, srcLane);
            float ae0 = __int_as_float(__shfl_sync(0xffffffffu, pl.y, srcLane));
            float ae1 = __int_as_float(__shfl_sync(0xffffffffu, pl.z, srcLane));
            if (srcLane < nthis) {
                float a = h ? ae1 : ae0;
                den += a;
                uint4 pk = __ldg((const uint4*)&g_h1h[(long)s * 128 + c8]);
                float2 p0 = __half22float2(*(const __half2*)&pk.x);
                float2 p1 = __half22float2(*(const __half2*)&pk.y);
                float2 p2 = __half22float2(*(const __half2*)&pk.z);
                float2 p3 = __half22float2(*(const __half2*)&pk.w);
                acc[0] += p0.x * a; acc[1] += p0.y * a;
                acc[2] += p1.x * a; acc[3] += p1.y * a;
                acc[4] += p2.x * a; acc[5] += p2.y * a;
                acc[6] += p3.x * a; acc[7] += p3.y * a;
            }
        }
    }

    // merge the two halves (same channel mapping in both)
    den += __shfl_xor_sync(0xffffffffu, den, 16);
#pragma unroll
    for (int k = 0; k < 8; k++) acc[k] += __shfl_xor_sync(0xffffffffu, acc[k], 16);

    float r = 1.f / (den + EPS);
    // normalize + bias + ELU, then project to layer 2 (W2 is [128,2] row-major)
    float4 bA = *(const float4*)&b1[c8];
    float4 bB = *(const float4*)&b1[c8 + 4];
    float vv[8];
    vv[0] = acc[0] * r + bA.x; vv[1] = acc[1] * r + bA.y;
    vv[2] = acc[2] * r + bA.z; vv[3] = acc[3] * r + bA.w;
    vv[4] = acc[4] * r + bB.x; vv[5] = acc[5] * r + bB.y;
    vv[6] = acc[6] * r + bB.z; vv[7] = acc[7] * r + bB.w;
#pragma unroll
    for (int k = 0; k < 8; k++) vv[k] = vv[k] > 0.f ? vv[k] : expm1f(vv[k]);

    float p0 = 0.f, p1 = 0.f;
#pragma unroll
    for (int k = 0; k < 8; k += 2) {
        float4 wv = *(const float4*)&W2[(c8 + k) * 2];
        p0 += vv[k] * wv.x + vv[k + 1] * wv.z;
        p1 += vv[k] * wv.y + vv[k + 1] * wv.w;
    }
#pragma unroll
    for (int off = 1; off <= 8; off <<= 1) {
        p0 += __shfl_xor_sync(0xffffffffu, p0, off);
        p1 += __shfl_xor_sync(0xffffffffu, p1, off);
    }
    if (lane == 0) {
        g_node2[w] = make_float4(p0, p1,
                                 p0 * as2[0] + p1 * as2[1],
                                 p0 * ad2[0] + p1 * ad2[1]);
    }
}

// ------------------------ K4: layer-2 aggregate (WARP per node) --------------
// lanes cover the node's CSR rows in parallel: coalesced CSR reads, one 16B
// node2 gather per edge, independent loads (high MLP), 3-value shfl reduce.
__global__ __launch_bounds__(256) void k_agg2(float* __restrict__ out,
                                              const float* __restrict__ b2, int N) {
    int w = (blockIdx.x * blockDim.x + threadIdx.x) >> 5;
    int lane = threadIdx.x & 31;
    if (w >= N) return;
    int beg = g_rowptr[w], end = g_rowptr[w + 1];
    float4 me = g_node2[w];              // {h0, h1, asrc2, adst2}
    float adn = me.w;

    float den = 0.f, a0 = 0.f, a1 = 0.f;
    for (int i0 = beg + lane; i0 < end; i0 += 32) {
        int4 pl = __ldg(&g_csr[i0]);
        float4 sn = __ldg(&g_node2[pl.x]);
        float ae = __expf(leaky(sn.z + adn + __int_as_float(pl.w)));
        den += ae;
        a0 += sn.x * ae;
        a1 += sn.y * ae;
    }
#pragma unroll
    for (int off = 16; off; off >>= 1) {
        den += __shfl_xor_sync(0xffffffffu, den, off);
        a0  += __shfl_xor_sync(0xffffffffu, a0, off);
        a1  += __shfl_xor_sync(0xffffffffu, a1, off);
    }
    if (lane == 0) {
        float es = __expf(leaky(me.z + adn));   // self-loop term
        den += es;
        a0 += me.x * es;
        a1 += me.y * es;
        float r = 1.f / (den + EPS);
        out[w * 2]     = a0 * r + b2[0];
        out[w * 2 + 1] = a1 * r + b2[1];
    }
}

// ------------------------ launch --------------------------------------------
extern "C" void kernel_launch(void* const* d_in, const int* in_sizes, int n_in,
                              void* d_out, int out_size) {
    const float* x   = (const float*)d_in[0];
    const int*   ei  = (const int*)  d_in[1];
    const float* ea  = (const float*)d_in[2];
    const float* W1  = (const float*)d_in[3];
    const float* We1 = (const float*)d_in[4];
    const float* as1 = (const float*)d_in[5];
    const float* ad1 = (const float*)d_in[6];
    const float* ae1 = (const float*)d_in[7];
    const float* b1  = (const float*)d_in[8];
    const float* W2  = (const float*)d_in[9];
    const float* We2 = (const float*)d_in[10];
    const float* as2 = (const float*)d_in[11];
    const float* ad2 = (const float*)d_in[12];
    const float* ae2 = (const float*)d_in[13];
    const float* b2  = (const float*)d_in[14];
    float* out = (float*)d_out;

    const int N = in_sizes[0] / 128;
    const int E = in_sizes[1] / 2;

    const int T = 256;
    const int gN  = (N + T - 1) / T;
    const int gNw = (N * 32 + T - 1) / T;
    const int gE  = (E + T - 1) / T;
    const int gM  = (N + GBM - 1) / GBM;
    const int nb  = (N + 1023) / 1024;
    (void)gN;

    // one-time side stream + fork/join events (host objects; no device allocs)
    static cudaStream_t sSide = nullptr;
    static cudaEvent_t evFork = nullptr, evJoin = nullptr;
    if (!sSide) {
        cudaStreamCreateWithFlags(&sSide, cudaStreamNonBlocking);
        cudaEventCreateWithFlags(&evFork, cudaEventDisableTiming);
        cudaEventCreateWithFlags(&evJoin, cudaEventDisableTiming);
    }

    // fork: GEMM alone on the side stream (nothing added to the binding branch)
    cudaEventRecord(evFork, 0);
    cudaStreamWaitEvent(sSide, evFork, 0);
    k_gemm1<<<gM, 256, 0, sSide>>>(x, W1, as1, ad1, N);
    cudaEventRecord(evJoin, sSide);

    // main stream: degree histogram (+parallel weight fold) + scan — fully
    // independent of the GEMM. g_deg is zero on entry (prev call's scan3).
    k_hist<<<gE, T>>>(ei, We1, ae1, We2, ae2, E);
    k_scan1<<<nb, 256>>>(N);
    k_scan3<<<(N + T - 1) / T, T>>>(N, E);

    // join: scatter needs asrc1/adst1 (gemm) AND rowptr/cursor (scan)
    cudaStreamWaitEvent(0, evJoin, 0);
    k_scatter<<<gE, T>>>(ei, ea, E);

    k_agg1<<<gNw, T>>>(b1, W2, as2, ad2, N);
    k_agg2<<<gNw, T>>>(out, b2, N);
}

// round 16
// speedup vs baseline: 1.1149x; 1.1149x over previous
#include <cuda_runtime.h>
#include <cuda_fp16.h>
#include <math.h>

#define MAXN 100000
#define MAXE 1600000
#define EPS 1e-16f

// ------------------------ scratch (device globals, no allocs) ---------------
__device__ __half g_h1h[MAXN * 128];     // layer-1 node projections (fp16)
__device__ float  g_asrc1[MAXN * 2];
__device__ float  g_adst1[MAXN * 2];

__device__ float4 g_node2[MAXN];         // {h2p0, h2p1, asrc2, adst2}

__device__ float g_weatt1[6];            // [head][k] folded edge-attn weights
__device__ float g_weatt2[3];

// CSR structures (rebuilt every call — deterministic work)
// g_deg is zero on entry (zero-initialized at load; re-zeroed by k_scan3 each call)
__device__ int  g_deg[MAXN];
__device__ int  g_rowptr[MAXN + 1];
__device__ int  g_cursor[MAXN];
__device__ int  g_blocksum[256];
__device__ int4 g_csr[MAXE];             // {src, f2i(ae0), f2i(ae1), f2i(edot2)}

// ------------------------ helpers -------------------------------------------
static __device__ __forceinline__ float leaky(float a) { return a > 0.f ? a : 0.2f * a; }

static __device__ __forceinline__ unsigned h2_bits(__half2 h) {
    union { __half2 h; unsigned u; } cvt;
    cvt.h = h;
    return cvt.u;
}

// fp16 tensor-core mma: D(16x8,f32) += A(16x16,f16) * B(16x8,f16)
static __device__ __forceinline__ void mma_f16(float* c, unsigned a0, unsigned a1,
                                               unsigned a2, unsigned a3,
                                               unsigned b0, unsigned b1) {
    asm volatile(
        "mma.sync.aligned.m16n8k16.row.col.f32.f16.f16.f32 "
        "{%0,%1,%2,%3}, {%4,%5,%6,%7}, {%8,%9}, {%0,%1,%2,%3};"
        : "+f"(c[0]), "+f"(c[1]), "+f"(c[2]), "+f"(c[3])
        : "r"(a0), "r"(a1), "r"(a2), "r"(a3), "r"(b0), "r"(b1));
}

// ------------------------ K1: h1 = x @ W1 via fp16 mma + fused att dots -----
// Tile 128 rows x 128 cols, K in chunks of 32 (= 2 k16 MMA steps).
// Smem staged as half2 with row stride 36 (36 mod 32 = 4 -> conflict-free
// fragment loads: lane addr = lg*36 + lt covers all 32 banks).
#define GBM 128
__global__ __launch_bounds__(256) void k_gemm1(const float* __restrict__ x,
                                               const float* __restrict__ W,
                                               const float* __restrict__ as1,
                                               const float* __restrict__ ad1, int N) {
    __shared__ __half2 xs[GBM][36];   // [row][k-pair]  (16 used per chunk)
    __shared__ __half2 wst[128][36];  // [col][k-pair]  (B stored col-major)
    const int tid = threadIdx.x;
    const int warp = tid >> 5, lane = tid & 31;
    const int lg = lane >> 2;        // group 0..7 (row within fragment)
    const int lt = lane & 3;         // thread in group
    const int rowBase = blockIdx.x * GBM;
    const int wr = warp * 16;        // warp's row offset within tile

    float acc[16][4];
#pragma unroll
    for (int i = 0; i < 16; i++)
        acc[i][0] = acc[i][1] = acc[i][2] = acc[i][3] = 0.f;

    for (int k0 = 0; k0 < 128; k0 += 32) {
        // stage x tile: 128 rows x 32 k (16 half2 per row)
        for (int i = tid; i < GBM * 8; i += 256) {
            int r = i >> 3, c4 = (i & 7) * 4;
            int gr = rowBase + r;
            float4 v = (gr < N) ? *(const float4*)&x[(long)gr * 128 + k0 + c4]
                                : make_float4(0.f, 0.f, 0.f, 0.f);
            xs[r][(c4 >> 1) + 0] = __floats2half2_rn(v.x, v.y);
            xs[r][(c4 >> 1) + 1] = __floats2half2_rn(v.z, v.w);
        }
        // stage W tile transposed: wst[col][j] = (W[k0+2j][col], W[k0+2j+1][col])
        for (int i = tid; i < 512; i += 256) {
            int j  = i >> 5;          // k-pair 0..15
            int cg = (i & 31) * 4;    // col group
            float4 vA = *(const float4*)&W[(long)(k0 + 2 * j) * 128 + cg];
            float4 vB = *(const float4*)&W[(long)(k0 + 2 * j + 1) * 128 + cg];
            wst[cg + 0][j] = __floats2half2_rn(vA.x, vB.x);
            wst[cg + 1][j] = __floats2half2_rn(vA.y, vB.y);
            wst[cg + 2][j] = __floats2half2_rn(vA.z, vB.z);
            wst[cg + 3][j] = __floats2half2_rn(vA.w, vB.w);
        }
        __syncthreads();
#pragma unroll
        for (int t16 = 0; t16 < 2; t16++) {
            int j0 = t16 * 8;
            unsigned a0 = h2_bits(xs[wr + lg][j0 + lt]);
            unsigned a1 = h2_bits(xs[wr + lg + 8][j0 + lt]);
            unsigned a2 = h2_bits(xs[wr + lg][j0 + lt + 4]);
            unsigned a3 = h2_bits(xs[wr + lg + 8][j0 + lt + 4]);
#pragma unroll
            for (int nt = 0; nt < 16; nt++) {
                unsigned b0 = h2_bits(wst[nt * 8 + lg][j0 + lt]);
                unsigned b1 = h2_bits(wst[nt * 8 + lg][j0 + lt + 4]);
                mma_f16(acc[nt], a0, a1, a2, a3, b0, b1);
            }
        }
        __syncthreads();
    }

    // epilogue: fp16 store + attention dot products (acc layout == k8 version)
    int rA = rowBase + wr + lg;
    int rB = rA + 8;
    float sA0 = 0.f, sA1 = 0.f, dA0 = 0.f, dA1 = 0.f;
    float sB0 = 0.f, sB1 = 0.f, dB0 = 0.f, dB1 = 0.f;
#pragma unroll
    for (int nt = 0; nt < 16; nt++) {
        int col = nt * 8 + lt * 2;
        if (rA < N)
            *(unsigned*)&g_h1h[(long)rA * 128 + col] =
                h2_bits(__floats2half2_rn(acc[nt][0], acc[nt][1]));
        if (rB < N)
            *(unsigned*)&g_h1h[(long)rB * 128 + col] =
                h2_bits(__floats2half2_rn(acc[nt][2], acc[nt][3]));
        float as0 = __ldg(&as1[col]), as1v = __ldg(&as1[col + 1]);
        float ad0 = __ldg(&ad1[col]), ad1v = __ldg(&ad1[col + 1]);
        if (nt < 8) {
            sA0 += acc[nt][0] * as0 + acc[nt][1] * as1v;
            dA0 += acc[nt][0] * ad0 + acc[nt][1] * ad1v;
            sB0 += acc[nt][2] * as0 + acc[nt][3] * as1v;
            dB0 += acc[nt][2] * ad0 + acc[nt][3] * ad1v;
        } else {
            sA1 += acc[nt][0] * as0 + acc[nt][1] * as1v;
            dA1 += acc[nt][0] * ad0 + acc[nt][1] * ad1v;
            sB1 += acc[nt][2] * as0 + acc[nt][3] * as1v;
            dB1 += acc[nt][2] * ad0 + acc[nt][3] * ad1v;
        }
    }
#pragma unroll
    for (int off = 1; off <= 2; off <<= 1) {
        sA0 += __shfl_xor_sync(0xffffffffu, sA0, off);
        sA1 += __shfl_xor_sync(0xffffffffu, sA1, off);
        dA0 += __shfl_xor_sync(0xffffffffu, dA0, off);
        dA1 += __shfl_xor_sync(0xffffffffu, dA1, off);
        sB0 += __shfl_xor_sync(0xffffffffu, sB0, off);
        sB1 += __shfl_xor_sync(0xffffffffu, sB1, off);
        dB0 += __shfl_xor_sync(0xffffffffu, dB0, off);
        dB1 += __shfl_xor_sync(0xffffffffu, dB1, off);
    }
    if (lt == 0) {
        if (rA < N) {
            g_asrc1[rA * 2] = sA0; g_asrc1[rA * 2 + 1] = sA1;
            g_adst1[rA * 2] = dA0; g_adst1[rA * 2 + 1] = dA1;
        }
        if (rB < N) {
            g_asrc1[rB * 2] = sB0; g_asrc1[rB * 2 + 1] = sB1;
            g_adst1[rB * 2] = dB0; g_adst1[rB * 2 + 1] = dB1;
        }
    }
}

// ------------------------ CSR build ------------------------------------------
// scalar hist; block 0 folds the edge-attention weights IN PARALLEL
// (warps 0-5: one 64-length dot each via shfl reduction; warp 6: layer-2 fold)
__global__ __launch_bounds__(256) void k_hist(const int* __restrict__ ei,
                                              const float* __restrict__ We1,
                                              const float* __restrict__ ae1,
                                              const float* __restrict__ We2,
                                              const float* __restrict__ ae2, int E) {
    int e = blockIdx.x * blockDim.x + threadIdx.x;
    if (e < E) atomicAdd(&g_deg[__ldg(&ei[E + e])], 1);
    if (blockIdx.x == 0) {
        int warp = threadIdx.x >> 5, lane = threadIdx.x & 31;
        if (warp < 6) {
            int h = warp / 3, k = warp % 3;   // g_weatt1 index = h*3+k = warp
            float s = We1[k * 128 + h * 64 + lane]      * ae1[h * 64 + lane]
                    + We1[k * 128 + h * 64 + lane + 32] * ae1[h * 64 + lane + 32];
#pragma unroll
            for (int off = 16; off; off >>= 1)
                s += __shfl_xor_sync(0xffffffffu, s, off);
            if (lane == 0) g_weatt1[warp] = s;
        } else if (warp == 6 && lane < 3) {
            g_weatt2[lane] = We2[lane * 2 + 0] * ae2[0] + We2[lane * 2 + 1] * ae2[1];
        }
    }
}

__global__ __launch_bounds__(256) void k_scan1(int N) {
    __shared__ int ssum[256];
    int t = threadIdx.x;
    int base = blockIdx.x * 1024;
    int idx = base + t * 4;
    int v0 = 0, v1 = 0, v2 = 0, v3 = 0;
    if (idx + 3 < N) {
        int4 v = *(const int4*)&g_deg[idx];
        v0 = v.x; v1 = v.y; v2 = v.z; v3 = v.w;
    } else {
        if (idx + 0 < N) v0 = g_deg[idx + 0];
        if (idx + 1 < N) v1 = g_deg[idx + 1];
        if (idx + 2 < N) v2 = g_deg[idx + 2];
        if (idx + 3 < N) v3 = g_deg[idx + 3];
    }
    int s0 = v0, s1 = s0 + v1, s2 = s1 + v2, s3 = s2 + v3;
    ssum[t] = s3;
    __syncthreads();
    for (int off = 1; off < 256; off <<= 1) {
        int add = (t >= off) ? ssum[t - off] : 0;
        __syncthreads();
        ssum[t] += add;
        __syncthreads();
    }
    int texcl = t ? ssum[t - 1] : 0;
    if (idx + 0 < N) g_rowptr[idx + 0] = texcl;
    if (idx + 1 < N) g_rowptr[idx + 1] = texcl + s0;
    if (idx + 2 < N) g_rowptr[idx + 2] = texcl + s1;
    if (idx + 3 < N) g_rowptr[idx + 3] = texcl + s2;
    if (t == 255) g_blocksum[blockIdx.x] = ssum[255];
}

// scan3 folds in the inter-block offset (prefix of blocksum) per block, and
// re-zeroes g_deg (already consumed by scan1) so the next call starts clean.
__global__ __launch_bounds__(256) void k_scan3(int N, int E) {
    __shared__ int sh[256];
    int t = threadIdx.x;
    int bucket = blockIdx.x >> 2;              // scan1 block containing this range
    sh[t] = (t < bucket) ? g_blocksum[t] : 0;  // bucket <= 97 < 256
    __syncthreads();
#pragma unroll
    for (int off = 128; off; off >>= 1) {
        if (t < off) sh[t] += sh[t + off];
        __syncthreads();
    }
    int offset = sh[0];
    int n = blockIdx.x * 256 + t;
    if (n < N) {
        int v = g_rowptr[n] + offset;
        g_rowptr[n] = v;
        g_cursor[n] = v;
        g_deg[n] = 0;                          // ready for next replay
    }
    if (blockIdx.x == 0 && t == 0) g_rowptr[N] = E;
}

// scatter (R9 form): computes exp(alpha) per head here, where adst1[d]/asrc1[s]
// gathers overlap the scattered store; payload is {src, ae0, ae1, edot2}.
__global__ __launch_bounds__(256) void k_scatter(const int* __restrict__ ei,
                                                 const float* __restrict__ ea, int E) {
    int e = blockIdx.x * blockDim.x + threadIdx.x;
    if (e >= E) return;
    int s = __ldg(&ei[e]), d = __ldg(&ei[E + e]);
    float e0 = __ldg(&ea[e * 3]), e1 = __ldg(&ea[e * 3 + 1]), e2 = __ldg(&ea[e * 3 + 2]);
    float2 asv = *(const float2*)&g_asrc1[s * 2];
    float2 adv = *(const float2*)&g_adst1[d * 2];
    float ae0 = __expf(leaky(asv.x + adv.x +
                  e0 * g_weatt1[0] + e1 * g_weatt1[1] + e2 * g_weatt1[2]));
    float ae1 = __expf(leaky(asv.y + adv.y +
                  e0 * g_weatt1[3] + e1 * g_weatt1[4] + e2 * g_weatt1[5]));
    float edot2 = e0 * g_weatt2[0] + e1 * g_weatt2[1] + e2 * g_weatt2[2];
    int pos = atomicAdd(&g_cursor[d], 1);
    g_csr[pos] = make_int4(s, __float_as_int(ae0), __float_as_int(ae1), __float_as_int(edot2));
}

// ------------------------ K3: fused layer-1 aggregate + ELU + layer-2 proj --
// one warp per dst node, HALF-WARP per edge: lane covers 8 fp16 channels
// (16B load), two edges in flight per iteration, register accumulation.
// (EXACT Round-9 body; epilogue writes the packed float4 node record.)
__global__ __launch_bounds__(256) void k_agg1(const float* __restrict__ b1,
                                              const float* __restrict__ W2,
                                              const float* __restrict__ as2,
                                              const float* __restrict__ ad2, int N) {
    int w = (blockIdx.x * blockDim.x + threadIdx.x) >> 5;
    int lane = threadIdx.x & 31;
    if (w >= N) return;
    const int half = lane >> 4;          // 0 = slot A, 1 = slot B
    const int hl = lane & 15;            // lane within half
    const int c8 = hl * 8;               // 8 fp16 channels starting here
    const int h = hl >> 3;               // head of these channels
    int beg = g_rowptr[w], end = g_rowptr[w + 1];

    float acc[8];
    float den = 0.f;

    // self-loop term: accumulated by half A only (merged via shfl_xor(16) later)
    {
        float2 asv = *(const float2*)&g_asrc1[w * 2];
        float2 adv = *(const float2*)&g_adst1[w * 2];
        float es0 = __expf(leaky(asv.x + adv.x));
        float es1 = __expf(leaky(asv.y + adv.y));
        float es = h ? es1 : es0;
        if (half == 0) {
            den = es;
            uint4 pk = *(const uint4*)&g_h1h[(long)w * 128 + c8];
            float2 p0 = __half22float2(*(const __half2*)&pk.x);
            float2 p1 = __half22float2(*(const __half2*)&pk.y);
            float2 p2 = __half22float2(*(const __half2*)&pk.z);
            float2 p3 = __half22float2(*(const __half2*)&pk.w);
            acc[0] = p0.x * es; acc[1] = p0.y * es;
            acc[2] = p1.x * es; acc[3] = p1.y * es;
            acc[4] = p2.x * es; acc[5] = p2.y * es;
            acc[6] = p3.x * es; acc[7] = p3.y * es;
        } else {
#pragma unroll
            for (int k = 0; k < 8; k++) acc[k] = 0.f;
        }
    }

    for (int i0 = beg; i0 < end; i0 += 32) {
        int nthis = min(32, end - i0);
        int iters = (nthis + 1) >> 1;        // warp-uniform trip count
        int4 pl = make_int4(0, 0, 0, 0);
        if (lane < nthis) pl = __ldg(&g_csr[i0 + lane]);
#pragma unroll 4
        for (int t = 0; t < iters; t++) {
            int srcLane = 2 * t + half;      // my half's edge in this pair
            int   s   = __shfl_sync(0xffffffffu, pl.x, srcLane);
            float ae0 = __int_as_float(__shfl_sync(0xffffffffu, pl.y, srcLane));
            float ae1 = __int_as_float(__shfl_sync(0xffffffffu, pl.z, srcLane));
            if (srcLane < nthis) {
                float a = h ? ae1 : ae0;
                den += a;
                uint4 pk = __ldg((const uint4*)&g_h1h[(long)s * 128 + c8]);
                float2 p0 = __half22float2(*(const __half2*)&pk.x);
                float2 p1 = __half22float2(*(const __half2*)&pk.y);
                float2 p2 = __half22float2(*(const __half2*)&pk.z);
                float2 p3 = __half22float2(*(const __half2*)&pk.w);
                acc[0] += p0.x * a; acc[1] += p0.y * a;
                acc[2] += p1.x * a; acc[3] += p1.y * a;
                acc[4] += p2.x * a; acc[5] += p2.y * a;
                acc[6] += p3.x * a; acc[7] += p3.y * a;
            }
        }
    }

    // merge the two halves (same channel mapping in both)
    den += __shfl_xor_sync(0xffffffffu, den, 16);
#pragma unroll
    for (int k = 0; k < 8; k++) acc[k] += __shfl_xor_sync(0xffffffffu, acc[k], 16);

    float r = 1.f / (den + EPS);
    // normalize + bias + ELU, then project to layer 2 (W2 is [128,2] row-major)
    float4 bA = *(const float4*)&b1[c8];
    float4 bB = *(const float4*)&b1[c8 + 4];
    float vv[8];
    vv[0] = acc[0] * r + bA.x; vv[1] = acc[1] * r + bA.y;
    vv[2] = acc[2] * r + bA.z; vv[3] = acc[3] * r + bA.w;
    vv[4] = acc[4] * r + bB.x; vv[5] = acc[5] * r + bB.y;
    vv[6] = acc[6] * r + bB.z; vv[7] = acc[7] * r + bB.w;
#pragma unroll
    for (int k = 0; k < 8; k++) vv[k] = vv[k] > 0.f ? vv[k] : expm1f(vv[k]);

    float p0 = 0.f, p1 = 0.f;
#pragma unroll
    for (int k = 0; k < 8; k += 2) {
        float4 wv = *(const float4*)&W2[(c8 + k) * 2];
        p0 += vv[k] * wv.x + vv[k + 1] * wv.z;
        p1 += vv[k] * wv.y + vv[k + 1] * wv.w;
    }
#pragma unroll
    for (int off = 1; off <= 8; off <<= 1) {
        p0 += __shfl_xor_sync(0xffffffffu, p0, off);
        p1 += __shfl_xor_sync(0xffffffffu, p1, off);
    }
    if (lane == 0) {
        g_node2[w] = make_float4(p0, p1,
                                 p0 * as2[0] + p1 * as2[1],
                                 p0 * ad2[0] + p1 * ad2[1]);
    }
}

// ------------------------ K4: layer-2 aggregate (WARP per node) --------------
__global__ __launch_bounds__(256) void k_agg2(float* __restrict__ out,
                                              const float* __restrict__ b2, int N) {
    int w = (blockIdx.x * blockDim.x + threadIdx.x) >> 5;
    int lane = threadIdx.x & 31;
    if (w >= N) return;
    int beg = g_rowptr[w], end = g_rowptr[w + 1];
    float4 me = g_node2[w];              // {h0, h1, asrc2, adst2}
    float adn = me.w;

    float den = 0.f, a0 = 0.f, a1 = 0.f;
    for (int i0 = beg + lane; i0 < end; i0 += 32) {
        int4 pl = __ldg(&g_csr[i0]);
        float4 sn = __ldg(&g_node2[pl.x]);
        float ae = __expf(leaky(sn.z + adn + __int_as_float(pl.w)));
        den += ae;
        a0 += sn.x * ae;
        a1 += sn.y * ae;
    }
#pragma unroll
    for (int off = 16; off; off >>= 1) {
        den += __shfl_xor_sync(0xffffffffu, den, off);
        a0  += __shfl_xor_sync(0xffffffffu, a0, off);
        a1  += __shfl_xor_sync(0xffffffffu, a1, off);
    }
    if (lane == 0) {
        float es = __expf(leaky(me.z + adn));   // self-loop term
        den += es;
        a0 += me.x * es;
        a1 += me.y * es;
        float r = 1.f / (den + EPS);
        out[w * 2]     = a0 * r + b2[0];
        out[w * 2 + 1] = a1 * r + b2[1];
    }
}

// ------------------------ launch --------------------------------------------
extern "C" void kernel_launch(void* const* d_in, const int* in_sizes, int n_in,
                              void* d_out, int out_size) {
    const float* x   = (const float*)d_in[0];
    const int*   ei  = (const int*)  d_in[1];
    const float* ea  = (const float*)d_in[2];
    const float* W1  = (const float*)d_in[3];
    const float* We1 = (const float*)d_in[4];
    const float* as1 = (const float*)d_in[5];
    const float* ad1 = (const float*)d_in[6];
    const float* ae1 = (const float*)d_in[7];
    const float* b1  = (const float*)d_in[8];
    const float* W2  = (const float*)d_in[9];
    const float* We2 = (const float*)d_in[10];
    const float* as2 = (const float*)d_in[11];
    const float* ad2 = (const float*)d_in[12];
    const float* ae2 = (const float*)d_in[13];
    const float* b2  = (const float*)d_in[14];
    float* out = (float*)d_out;

    const int N = in_sizes[0] / 128;
    const int E = in_sizes[1] / 2;

    const int T = 256;
    const int gN  = (N + T - 1) / T;
    const int gNw = (N * 32 + T - 1) / T;
    const int gE  = (E + T - 1) / T;
    const int gM  = (N + GBM - 1) / GBM;
    const int nb  = (N + 1023) / 1024;

    // one-time side stream + fork/join events (host objects; no device allocs)
    static cudaStream_t sSide = nullptr;
    static cudaEvent_t evFork = nullptr, evJoin = nullptr;
    if (!sSide) {
        cudaStreamCreateWithFlags(&sSide, cudaStreamNonBlocking);
        cudaEventCreateWithFlags(&evFork, cudaEventDisableTiming);
        cudaEventCreateWithFlags(&evJoin, cudaEventDisableTiming);
    }

    // fork: GEMM alone on the side stream (nothing added to the binding branch)
    cudaEventRecord(evFork, 0);
    cudaStreamWaitEvent(sSide, evFork, 0);
    k_gemm1<<<gM, 256, 0, sSide>>>(x, W1, as1, ad1, N);
    cudaEventRecord(evJoin, sSide);

    // main stream: degree histogram (+parallel weight fold) + scan — fully
    // independent of the GEMM. g_deg is zero on entry (prev call's scan3).
    k_hist<<<gE, T>>>(ei, We1, ae1, We2, ae2, E);
    k_scan1<<<nb, 256>>>(N);
    k_scan3<<<gN, T>>>(N, E);

    // join: scatter needs asrc1/adst1 (gemm) AND rowptr/cursor (scan)
    cudaStreamWaitEvent(0, evJoin, 0);
    k_scatter<<<gE, T>>>(ei, ea, E);

    k_agg1<<<gNw, T>>>(b1, W2, as2, ad2, N);
    k_agg2<<<gNw, T>>>(out, b2, N);
}